// round 1
// baseline (speedup 1.0000x reference)
#include <cuda_runtime.h>
#include <cuda_bf16.h>
#include <math.h>

// ---------------------------------------------------------------------------
// Problem constants
// ---------------------------------------------------------------------------
#define BB 2
#define SS 2048
#define HH 2304
#define NHEAD 8
#define NKV 4
#define HD 256
#define FF 9216
#define NTOK (BB * SS)            // 4096
#define QDIM (NHEAD * HD)          // 2048
#define KVDIM (NKV * HD)           // 1024
#define SOFTCAP 50.0f
#define ATT_SCALE 0.0625f          // 256^-0.5
#define RMS_EPS 1e-6f

// ---------------------------------------------------------------------------
// Scratch (static device memory; no allocations allowed)
// ---------------------------------------------------------------------------
__device__ float g_h   [(size_t)NTOK * HH];     // rmsnorm(x, g_in)
__device__ float g_q   [(size_t)NTOK * QDIM];
__device__ float g_k   [(size_t)NTOK * KVDIM];
__device__ float g_v   [(size_t)NTOK * KVDIM];
__device__ float g_o   [(size_t)NTOK * QDIM];   // attention output
__device__ float g_att [(size_t)NTOK * HH];     // o @ wo
__device__ float g_h2  [(size_t)NTOK * HH];     // residual 1
__device__ float g_f   [(size_t)NTOK * HH];     // pre-ff norm
__device__ float g_gate[(size_t)NTOK * FF];     // gate (then geglu product, in place)
__device__ float g_up  [(size_t)NTOK * FF];
__device__ float g_mlp [(size_t)NTOK * HH];

// ---------------------------------------------------------------------------
// RMSNorm (+ optional residual add):  out = [res +] x * rsqrt(mean(x^2)+eps) * (1+g)
// one block per row, H = 2304 = 576 float4
// ---------------------------------------------------------------------------
__global__ __launch_bounds__(256) void rmsnorm_kernel(
    const float* __restrict__ in, const float* __restrict__ g,
    const float* __restrict__ res, float* __restrict__ out)
{
    int row = blockIdx.x;
    const float4* x4 = (const float4*)(in + (size_t)row * HH);
    const float4* g4 = (const float4*)g;
    const float4* r4 = res ? (const float4*)(res + (size_t)row * HH) : nullptr;
    float4* o4 = (float4*)(out + (size_t)row * HH);
    int t = threadIdx.x;

    float ss = 0.f;
    for (int i = t; i < HH / 4; i += 256) {
        float4 v = x4[i];
        ss += v.x * v.x + v.y * v.y + v.z * v.z + v.w * v.w;
    }
    // reduce
    #pragma unroll
    for (int off = 16; off > 0; off >>= 1)
        ss += __shfl_xor_sync(0xffffffffu, ss, off);
    __shared__ float red[8];
    __shared__ float s_inv;
    if ((t & 31) == 0) red[t >> 5] = ss;
    __syncthreads();
    if (t == 0) {
        float tot = 0.f;
        #pragma unroll
        for (int i = 0; i < 8; i++) tot += red[i];
        s_inv = rsqrtf(tot / (float)HH + RMS_EPS);
    }
    __syncthreads();
    float inv = s_inv;

    for (int i = t; i < HH / 4; i += 256) {
        float4 v = x4[i];
        float4 gv = g4[i];
        float4 o;
        o.x = v.x * inv * (1.f + gv.x);
        o.y = v.y * inv * (1.f + gv.y);
        o.z = v.z * inv * (1.f + gv.z);
        o.w = v.w * inv * (1.f + gv.w);
        if (r4) {
            float4 rv = r4[i];
            o.x += rv.x; o.y += rv.y; o.z += rv.z; o.w += rv.w;
        }
        o4[i] = o;
    }
}

// ---------------------------------------------------------------------------
// SGEMM: C[M,N] = A[M,K] @ B[K,N]  (row-major, M%128==0, N%128==0, K%8==0)
// 128x128 block tile, BK=8, 8x8 microtile, 256 threads
// ---------------------------------------------------------------------------
#define GBM 128
#define GBN 128
#define GBK 8
__global__ __launch_bounds__(256) void sgemm_kernel(
    const float* __restrict__ A, const float* __restrict__ B,
    float* __restrict__ C, int M, int N, int K)
{
    __shared__ float As[GBK][GBM];
    __shared__ float Bs[GBK][GBN];

    int t = threadIdx.x;
    int bm = blockIdx.y * GBM;
    int bn = blockIdx.x * GBN;

    int rowA = t >> 1;                 // 0..127
    int colA = (t & 1) * 4;            // 0 or 4
    int rowB = t >> 5;                 // 0..7
    int colB = (t & 31) * 4;           // 0..124

    int ty = t >> 4;                   // 0..15
    int tx = t & 15;                   // 0..15

    const float* Ab = A + (size_t)(bm + rowA) * K + colA;
    const float* Bb = B + (size_t)rowB * N + bn + colB;

    float acc[8][8];
    #pragma unroll
    for (int i = 0; i < 8; i++)
        #pragma unroll
        for (int j = 0; j < 8; j++) acc[i][j] = 0.f;

    for (int k0 = 0; k0 < K; k0 += GBK) {
        float4 a4 = *(const float4*)(Ab + k0);
        As[colA + 0][rowA] = a4.x;
        As[colA + 1][rowA] = a4.y;
        As[colA + 2][rowA] = a4.z;
        As[colA + 3][rowA] = a4.w;
        *(float4*)&Bs[rowB][colB] = *(const float4*)(Bb + (size_t)k0 * N);
        __syncthreads();

        #pragma unroll
        for (int k = 0; k < GBK; k++) {
            float4 a0 = *(const float4*)&As[k][ty * 8];
            float4 a1 = *(const float4*)&As[k][ty * 8 + 4];
            float4 b0 = *(const float4*)&Bs[k][tx * 8];
            float4 b1 = *(const float4*)&Bs[k][tx * 8 + 4];
            float ra[8] = {a0.x, a0.y, a0.z, a0.w, a1.x, a1.y, a1.z, a1.w};
            float rb[8] = {b0.x, b0.y, b0.z, b0.w, b1.x, b1.y, b1.z, b1.w};
            #pragma unroll
            for (int i = 0; i < 8; i++)
                #pragma unroll
                for (int j = 0; j < 8; j++)
                    acc[i][j] = fmaf(ra[i], rb[j], acc[i][j]);
        }
        __syncthreads();
    }

    #pragma unroll
    for (int i = 0; i < 8; i++) {
        float* cp = C + (size_t)(bm + ty * 8 + i) * N + bn + tx * 8;
        float4 c0 = {acc[i][0], acc[i][1], acc[i][2], acc[i][3]};
        float4 c1 = {acc[i][4], acc[i][5], acc[i][6], acc[i][7]};
        *(float4*)cp = c0;
        *(float4*)(cp + 4) = c1;
    }
}

// ---------------------------------------------------------------------------
// RoPE, in place. buf: [NTOK, nh*HD]. One thread per (token, head, d<128) pair.
// ---------------------------------------------------------------------------
__global__ void rope_kernel(float* __restrict__ buf, int nh, int total)
{
    int idx = blockIdx.x * blockDim.x + threadIdx.x;
    if (idx >= total) return;
    int d = idx & 127;
    int rest = idx >> 7;
    int head = rest % nh;
    int tok = rest / nh;
    int pos = tok & (SS - 1);

    float inv = powf(10000.f, -(float)(2 * d) / (float)HD);
    float ang = (float)pos * inv;
    float s, c;
    sincosf(ang, &s, &c);

    float* p = buf + (size_t)tok * (nh * HD) + head * HD + d;
    float lo = p[0];
    float hi = p[128];
    p[0]   = lo * c - hi * s;
    p[128] = hi * c + lo * s;
}

// ---------------------------------------------------------------------------
// Flash attention, causal, GQA (rep=2), softcap.
// grid (S/64, NHEAD, BB), 256 threads. Row r owned by 4-thread quad; each quad
// thread owns a 64-wide slice of HD. q row + O accumulator in registers.
// dyn smem: Ks[32][256] + Vs[32][256] + Sp[64][32] = 73728 B
// ---------------------------------------------------------------------------
#define FA_BQ 64
#define FA_BK 32
__global__ __launch_bounds__(256) void flash_kernel(
    const float* __restrict__ Q, const float* __restrict__ K,
    const float* __restrict__ V, float* __restrict__ O)
{
    extern __shared__ float sm[];
    float* Ks = sm;                         // [32][256]
    float* Vs = sm + FA_BK * HD;            // [32][256]
    float* Sp = sm + 2 * FA_BK * HD;        // [64][32]

    int t = threadIdx.x;
    int r = t >> 2;         // 0..63 row within q tile
    int cp = t & 3;         // quad slice
    int q0 = blockIdx.x * FA_BQ;
    int h = blockIdx.y;
    int b = blockIdx.z;
    int kvh = h >> 1;
    int qg = q0 + r;

    // load q row slice into regs
    float qr[64];
    {
        const float* qp = Q + ((size_t)(b * SS + qg) * QDIM) + h * HD + cp * 64;
        #pragma unroll
        for (int i = 0; i < 16; i++) {
            float4 v4 = *(const float4*)(qp + i * 4);
            qr[i * 4 + 0] = v4.x; qr[i * 4 + 1] = v4.y;
            qr[i * 4 + 2] = v4.z; qr[i * 4 + 3] = v4.w;
        }
    }

    float o[64];
    #pragma unroll
    for (int i = 0; i < 64; i++) o[i] = 0.f;
    float m = -INFINITY, l = 0.f;

    int ntiles = q0 / FA_BK + 2;   // covers k <= q0+63

    for (int kt = 0; kt < ntiles; kt++) {
        int base = kt * FA_BK;
        // cooperative load of K,V tiles: 32*256 floats = 2048 float4 each
        #pragma unroll
        for (int i = 0; i < 8; i++) {
            int e = t + i * 256;
            int krow = e >> 6;
            int kcol = (e & 63) * 4;
            size_t goff = ((size_t)(b * SS + base + krow) * KVDIM) + kvh * HD + kcol;
            *(float4*)&Ks[krow * HD + kcol] = *(const float4*)(K + goff);
            *(float4*)&Vs[krow * HD + kcol] = *(const float4*)(V + goff);
        }
        __syncthreads();

        // pass 1: scores for this tile
        float tmax = -INFINITY;
        #pragma unroll 4
        for (int kk = 0; kk < FA_BK; kk++) {
            const float* kr = &Ks[kk * HD + cp * 64];
            float acc = 0.f;
            #pragma unroll
            for (int i = 0; i < 16; i++) {
                float4 k4 = *(const float4*)(kr + i * 4);
                acc = fmaf(qr[i * 4 + 0], k4.x, acc);
                acc = fmaf(qr[i * 4 + 1], k4.y, acc);
                acc = fmaf(qr[i * 4 + 2], k4.z, acc);
                acc = fmaf(qr[i * 4 + 3], k4.w, acc);
            }
            acc += __shfl_xor_sync(0xffffffffu, acc, 1);
            acc += __shfl_xor_sync(0xffffffffu, acc, 2);
            float sc = acc * ATT_SCALE;
            sc = SOFTCAP * tanhf(sc * (1.0f / SOFTCAP));
            int kg = base + kk;
            if (kg > qg) sc = -INFINITY;
            tmax = fmaxf(tmax, sc);
            if (cp == 0) Sp[r * FA_BK + kk] = sc;
        }
        __syncwarp();

        float mn = fmaxf(m, tmax);
        float alpha = __expf(m - mn);
        m = mn;
        l *= alpha;
        #pragma unroll
        for (int i = 0; i < 64; i++) o[i] *= alpha;

        // pass 2: p = exp(s - m), accumulate l and O
        #pragma unroll 2
        for (int kk = 0; kk < FA_BK; kk++) {
            float p = __expf(Sp[r * FA_BK + kk] - mn);
            l += p;
            const float* vr = &Vs[kk * HD + cp * 64];
            #pragma unroll
            for (int i = 0; i < 16; i++) {
                float4 v4 = *(const float4*)(vr + i * 4);
                o[i * 4 + 0] = fmaf(p, v4.x, o[i * 4 + 0]);
                o[i * 4 + 1] = fmaf(p, v4.y, o[i * 4 + 1]);
                o[i * 4 + 2] = fmaf(p, v4.z, o[i * 4 + 2]);
                o[i * 4 + 3] = fmaf(p, v4.w, o[i * 4 + 3]);
            }
        }
        __syncthreads();
    }

    float invl = 1.f / l;
    float* op = O + ((size_t)(b * SS + qg) * QDIM) + h * HD + cp * 64;
    #pragma unroll
    for (int i = 0; i < 16; i++) {
        float4 v4 = {o[i * 4 + 0] * invl, o[i * 4 + 1] * invl,
                     o[i * 4 + 2] * invl, o[i * 4 + 3] * invl};
        *(float4*)(op + i * 4) = v4;
    }
}

// ---------------------------------------------------------------------------
// GeGLU elementwise: out[i] = gelu_tanh(gate[i]) * up[i]  (out may alias gate)
// ---------------------------------------------------------------------------
__global__ void geglu_kernel(const float* __restrict__ gate,
                             const float* __restrict__ up,
                             float* __restrict__ out, int n)
{
    int i = blockIdx.x * blockDim.x + threadIdx.x;
    if (i >= n) return;
    float x = gate[i];
    float x3 = x * x * x;
    float tg = tanhf(0.7978845608028654f * (x + 0.044715f * x3));
    out[i] = 0.5f * x * (1.f + tg) * up[i];
}

// ---------------------------------------------------------------------------
// launch
// ---------------------------------------------------------------------------
static inline void launch_gemm(const float* A, const float* B, float* C,
                               int M, int N, int K)
{
    dim3 grid(N / GBN, M / GBM);
    sgemm_kernel<<<grid, 256>>>(A, B, C, M, N, K);
}

extern "C" void kernel_launch(void* const* d_in, const int* in_sizes, int n_in,
                              void* d_out, int out_size)
{
    const float* x        = (const float*)d_in[0];
    // d_in[1] = mask (causal, reconstructed in-kernel)
    const float* wq       = (const float*)d_in[2];
    const float* wk       = (const float*)d_in[3];
    const float* wv       = (const float*)d_in[4];
    const float* wo       = (const float*)d_in[5];
    const float* w_gate   = (const float*)d_in[6];
    const float* w_up     = (const float*)d_in[7];
    const float* w_down   = (const float*)d_in[8];
    const float* gin      = (const float*)d_in[9];
    const float* gpa      = (const float*)d_in[10];
    const float* gpf      = (const float*)d_in[11];
    const float* gpo      = (const float*)d_in[12];
    float* out = (float*)d_out;

    float *p_h, *p_q, *p_k, *p_v, *p_o, *p_att, *p_h2, *p_f, *p_gate, *p_up, *p_mlp;
    cudaGetSymbolAddress((void**)&p_h,    g_h);
    cudaGetSymbolAddress((void**)&p_q,    g_q);
    cudaGetSymbolAddress((void**)&p_k,    g_k);
    cudaGetSymbolAddress((void**)&p_v,    g_v);
    cudaGetSymbolAddress((void**)&p_o,    g_o);
    cudaGetSymbolAddress((void**)&p_att,  g_att);
    cudaGetSymbolAddress((void**)&p_h2,   g_h2);
    cudaGetSymbolAddress((void**)&p_f,    g_f);
    cudaGetSymbolAddress((void**)&p_gate, g_gate);
    cudaGetSymbolAddress((void**)&p_up,   g_up);
    cudaGetSymbolAddress((void**)&p_mlp,  g_mlp);

    static const int FLASH_SMEM = (2 * FA_BK * HD + FA_BQ * FA_BK) * 4; // 73728
    cudaFuncSetAttribute(flash_kernel,
                         cudaFuncAttributeMaxDynamicSharedMemorySize, FLASH_SMEM);

    // 1. h = rmsnorm(x, g_in)
    rmsnorm_kernel<<<NTOK, 256>>>(x, gin, nullptr, p_h);

    // 2. QKV projections
    launch_gemm(p_h, wq, p_q, NTOK, QDIM, HH);
    launch_gemm(p_h, wk, p_k, NTOK, KVDIM, HH);
    launch_gemm(p_h, wv, p_v, NTOK, KVDIM, HH);

    // 3. RoPE in place
    {
        int tq = NTOK * NHEAD * 128;
        rope_kernel<<<(tq + 255) / 256, 256>>>(p_q, NHEAD, tq);
        int tk = NTOK * NKV * 128;
        rope_kernel<<<(tk + 255) / 256, 256>>>(p_k, NKV, tk);
    }

    // 4. attention
    {
        dim3 grid(SS / FA_BQ, NHEAD, BB);
        flash_kernel<<<grid, 256, FLASH_SMEM>>>(p_q, p_k, p_v, p_o);
    }

    // 5. output projection
    launch_gemm(p_o, wo, p_att, NTOK, HH, QDIM);

    // 6. h2 = x + rmsnorm(att, g_post_attn)
    rmsnorm_kernel<<<NTOK, 256>>>(p_att, gpa, x, p_h2);

    // 7. f = rmsnorm(h2, g_pre_ff)
    rmsnorm_kernel<<<NTOK, 256>>>(p_h2, gpf, nullptr, p_f);

    // 8. MLP
    launch_gemm(p_f, w_gate, p_gate, NTOK, FF, HH);
    launch_gemm(p_f, w_up,   p_up,   NTOK, FF, HH);
    {
        int n = NTOK * FF;
        geglu_kernel<<<(n + 255) / 256, 256>>>(p_gate, p_up, p_gate, n);
    }
    launch_gemm(p_gate, w_down, p_mlp, NTOK, HH, FF);

    // 9. out = h2 + rmsnorm(mlp, g_post_ff)
    rmsnorm_kernel<<<NTOK, 256>>>(p_mlp, gpo, p_h2, out);
}

// round 4
// speedup vs baseline: 1.6780x; 1.6780x over previous
#include <cuda_runtime.h>
#include <cuda_bf16.h>
#include <math.h>
#include <stdint.h>

// ---------------------------------------------------------------------------
// Problem constants
// ---------------------------------------------------------------------------
#define BB 2
#define SS 2048
#define HH 2304
#define NHEAD 8
#define NKV 4
#define HD 256
#define FF 9216
#define NTOK (BB * SS)             // 4096
#define QDIM (NHEAD * HD)          // 2048
#define KVDIM (NKV * HD)           // 1024
#define SOFTCAP 50.0f
#define ATT_SCALE 0.0625f          // 256^-0.5
#define RMS_EPS 1e-6f

// ---------------------------------------------------------------------------
// Static scratch (no allocations allowed)
// ---------------------------------------------------------------------------
__device__ __align__(16) float g_q   [(size_t)NTOK * QDIM];
__device__ __align__(16) float g_k   [(size_t)NTOK * KVDIM];
__device__ __align__(16) float g_v   [(size_t)NTOK * KVDIM];
__device__ __align__(16) float g_att [(size_t)NTOK * HH];
__device__ __align__(16) float g_h2  [(size_t)NTOK * HH];
__device__ __align__(16) float g_gate[(size_t)NTOK * FF];
__device__ __align__(16) float g_up  [(size_t)NTOK * FF];
__device__ __align__(16) float g_mlp [(size_t)NTOK * HH];

// bf16 split activations (GEMM A operands)
__device__ __align__(16) __nv_bfloat16 s_hh[(size_t)NTOK * HH];
__device__ __align__(16) __nv_bfloat16 s_hl[(size_t)NTOK * HH];
__device__ __align__(16) __nv_bfloat16 s_oh[(size_t)NTOK * QDIM];
__device__ __align__(16) __nv_bfloat16 s_ol[(size_t)NTOK * QDIM];
__device__ __align__(16) __nv_bfloat16 s_fh[(size_t)NTOK * HH];
__device__ __align__(16) __nv_bfloat16 s_fl[(size_t)NTOK * HH];
__device__ __align__(16) __nv_bfloat16 s_gh[(size_t)NTOK * FF];
__device__ __align__(16) __nv_bfloat16 s_gl[(size_t)NTOK * FF];

// transposed, split weights: [N, K] row-major bf16 hi/lo
__device__ __align__(16) __nv_bfloat16 t_qh[(size_t)QDIM * HH],  t_ql[(size_t)QDIM * HH];
__device__ __align__(16) __nv_bfloat16 t_kh[(size_t)KVDIM * HH], t_kl[(size_t)KVDIM * HH];
__device__ __align__(16) __nv_bfloat16 t_vh[(size_t)KVDIM * HH], t_vl[(size_t)KVDIM * HH];
__device__ __align__(16) __nv_bfloat16 t_oh[(size_t)HH * QDIM],  t_ol[(size_t)HH * QDIM];
__device__ __align__(16) __nv_bfloat16 t_gh[(size_t)FF * HH],    t_gl[(size_t)FF * HH];
__device__ __align__(16) __nv_bfloat16 t_uh[(size_t)FF * HH],    t_ul[(size_t)FF * HH];
__device__ __align__(16) __nv_bfloat16 t_dh[(size_t)HH * FF],    t_dl[(size_t)HH * FF];

// ---------------------------------------------------------------------------
// PTX helpers (baseline compute_103 features only: cp.async, ldmatrix, mma.sync)
// ---------------------------------------------------------------------------
__device__ __forceinline__ uint32_t smem_u32(const void* p) {
    uint32_t a;
    asm("{ .reg .u64 t; cvta.to.shared.u64 t, %1; cvt.u32.u64 %0, t; }"
        : "=r"(a) : "l"(p));
    return a;
}

__device__ __forceinline__ void cp16(uint32_t saddr, const void* gaddr) {
    asm volatile("cp.async.cg.shared.global [%0], [%1], 16;\n"
                 :: "r"(saddr), "l"(gaddr));
}
__device__ __forceinline__ void cp_commit() {
    asm volatile("cp.async.commit_group;" ::: "memory");
}
__device__ __forceinline__ void cp_wait1() {
    asm volatile("cp.async.wait_group 1;" ::: "memory");
}

__device__ __forceinline__ void ldsm4(uint32_t* r, uint32_t addr) {
    asm volatile("ldmatrix.sync.aligned.m8n8.x4.shared.b16 {%0,%1,%2,%3}, [%4];"
                 : "=r"(r[0]), "=r"(r[1]), "=r"(r[2]), "=r"(r[3]) : "r"(addr));
}

__device__ __forceinline__ void mma16816(float* d, const uint32_t* a, const uint32_t* b) {
    asm volatile(
        "mma.sync.aligned.m16n8k16.row.col.f32.bf16.bf16.f32 "
        "{%0,%1,%2,%3}, {%4,%5,%6,%7}, {%8,%9}, {%0,%1,%2,%3};"
        : "+f"(d[0]), "+f"(d[1]), "+f"(d[2]), "+f"(d[3])
        : "r"(a[0]), "r"(a[1]), "r"(a[2]), "r"(a[3]), "r"(b[0]), "r"(b[1]));
}

__device__ __forceinline__ void split_bf16(float v, __nv_bfloat16& h, __nv_bfloat16& l) {
    h = __float2bfloat16(v);
    l = __float2bfloat16(v - __bfloat162float(h));
}

union BF4 { __nv_bfloat16 b[4]; uint2 u; };

// ---------------------------------------------------------------------------
// split-bf16 tensor-core GEMM: C[M,N] = (Ah+Al)[M,K] @ (Bh+Bl)^T  (B is [N,K])
// 128x128 CTA tile, BK=64, 2-stage cp.async, 8 warps (2x4), warp tile 64x32.
// Three mma passes per fragment pair: AhBh + AhBl + AlBh (fp32 accum).
// SMEM rows padded to 144 B -> conflict-free ldmatrix.
// ---------------------------------------------------------------------------
#define BKK   64
#define ROWB  (BKK * 2 + 16)          // 144 bytes per 128-row operand tile row
#define TILEB (128 * ROWB)            // 18432
#define STAGEB (4 * TILEB)            // Ah, Al, Bh, Bl
#define GT_SMEM (2 * STAGEB)          // 147456

__global__ __launch_bounds__(256, 1)
void tc_gemm(const __nv_bfloat16* __restrict__ Ah, const __nv_bfloat16* __restrict__ Al,
             const __nv_bfloat16* __restrict__ Bh, const __nv_bfloat16* __restrict__ Bl,
             float* __restrict__ C, int M, int N, int K)
{
    extern __shared__ __align__(16) char dynsm[];
    uint32_t tbase = smem_u32(dynsm);
    int tid = threadIdx.x;
    int wid = tid >> 5;
    int lane = tid & 31;

    int bm = blockIdx.y * 128;
    int bn = blockIdx.x * 128;

    const __nv_bfloat16* Ahb = Ah + (size_t)bm * K;
    const __nv_bfloat16* Alb = Al + (size_t)bm * K;
    const __nv_bfloat16* Bhb = Bh + (size_t)bn * K;
    const __nv_bfloat16* Blb = Bl + (size_t)bn * K;

    int nchunks = K >> 6;   // K / 64

    auto load_stage = [&](int s, int chunk) {
        uint32_t sb = tbase + s * STAGEB;
        size_t kof = (size_t)chunk * BKK;
        #pragma unroll
        for (int j = 0; j < 4; j++) {
            int e = tid + j * 256;        // 0..1023
            int row = e >> 3;             // 0..127
            int c = e & 7;                // 16B chunk
            uint32_t soff = (uint32_t)(row * ROWB + c * 16);
            size_t g = (size_t)row * K + kof + c * 8;
            cp16(sb + soff,             Ahb + g);
            cp16(sb + TILEB + soff,     Alb + g);
            cp16(sb + 2 * TILEB + soff, Bhb + g);
            cp16(sb + 3 * TILEB + soff, Blb + g);
        }
        cp_commit();
    };

    load_stage(0, 0);
    if (nchunks > 1) load_stage(1, 1); else cp_commit();

    int wy = wid >> 2;                 // 0..1  -> m offset 64*wy
    int wx = wid & 3;                  // 0..3  -> n offset 32*wx

    float acc[4][4][4];
    #pragma unroll
    for (int mt = 0; mt < 4; mt++)
        #pragma unroll
        for (int nt = 0; nt < 4; nt++)
            #pragma unroll
            for (int j = 0; j < 4; j++) acc[mt][nt][j] = 0.f;

    // ldmatrix per-lane address components
    int ra = lane & 15;                // A row within 16
    int caoff = (lane >> 4) * 8;       // A k half
    int rb = ((lane >> 4) << 3) + (lane & 7);   // B row within 16
    int cboff = ((lane >> 3) & 1) * 8;          // B k half

    for (int i = 0; i < nchunks; i++) {
        int s = i & 1;
        cp_wait1();
        __syncthreads();

        uint32_t sA_h = tbase + s * STAGEB;
        uint32_t sA_l = sA_h + TILEB;
        uint32_t sB_h = sA_h + 2 * TILEB;
        uint32_t sB_l = sA_h + 3 * TILEB;

        #pragma unroll
        for (int ks = 0; ks < 4; ks++) {
            uint32_t ah[4][4], al[4][4], bh[4][2], bl[4][2];
            #pragma unroll
            for (int mt = 0; mt < 4; mt++) {
                uint32_t off = (uint32_t)((wy * 64 + mt * 16 + ra) * ROWB
                                          + (ks * 16 + caoff) * 2);
                ldsm4(ah[mt], sA_h + off);
                ldsm4(al[mt], sA_l + off);
            }
            #pragma unroll
            for (int p = 0; p < 2; p++) {
                uint32_t off = (uint32_t)((wx * 32 + p * 16 + rb) * ROWB
                                          + (ks * 16 + cboff) * 2);
                uint32_t t4[4];
                ldsm4(t4, sB_h + off);
                bh[2 * p][0] = t4[0]; bh[2 * p][1] = t4[1];
                bh[2 * p + 1][0] = t4[2]; bh[2 * p + 1][1] = t4[3];
                ldsm4(t4, sB_l + off);
                bl[2 * p][0] = t4[0]; bl[2 * p][1] = t4[1];
                bl[2 * p + 1][0] = t4[2]; bl[2 * p + 1][1] = t4[3];
            }
            #pragma unroll
            for (int mt = 0; mt < 4; mt++)
                #pragma unroll
                for (int nt = 0; nt < 4; nt++) {
                    mma16816(acc[mt][nt], ah[mt], bh[nt]);
                    mma16816(acc[mt][nt], ah[mt], bl[nt]);
                    mma16816(acc[mt][nt], al[mt], bh[nt]);
                }
        }
        __syncthreads();
        if (i + 2 < nchunks) load_stage(s, i + 2);
        else cp_commit();   // keep group accounting consistent
    }

    // epilogue: C fragment rows lane>>2 (+8), cols 2*(lane&3)
    int er = lane >> 2;
    int ec = (lane & 3) * 2;
    #pragma unroll
    for (int mt = 0; mt < 4; mt++) {
        #pragma unroll
        for (int nt = 0; nt < 4; nt++) {
            float* c0 = C + (size_t)(bm + wy * 64 + mt * 16 + er) * N
                          + bn + wx * 32 + nt * 8 + ec;
            *(float2*)c0 = make_float2(acc[mt][nt][0], acc[mt][nt][1]);
            float* c1 = c0 + (size_t)8 * N;
            *(float2*)c1 = make_float2(acc[mt][nt][2], acc[mt][nt][3]);
        }
    }
}

// ---------------------------------------------------------------------------
// Weight prep: W[K,N] fp32 -> WT hi/lo [N,K] bf16.  grid(N/32, K/32), block(32,8)
// ---------------------------------------------------------------------------
__global__ void wprep_kernel(const float* __restrict__ W,
                             __nv_bfloat16* __restrict__ Th,
                             __nv_bfloat16* __restrict__ Tl, int K, int N)
{
    __shared__ float t[32][33];
    int n0 = blockIdx.x * 32, k0 = blockIdx.y * 32;
    int tx = threadIdx.x, ty = threadIdx.y;
    #pragma unroll
    for (int r = 0; r < 4; r++) {
        int k = ty + r * 8;
        t[k][tx] = W[(size_t)(k0 + k) * N + n0 + tx];
    }
    __syncthreads();
    #pragma unroll
    for (int r = 0; r < 4; r++) {
        int nl = ty + r * 8;
        float v = t[tx][nl];
        __nv_bfloat16 h, l;
        split_bf16(v, h, l);
        size_t o = (size_t)(n0 + nl) * K + k0 + tx;
        Th[o] = h;
        Tl[o] = l;
    }
}

// ---------------------------------------------------------------------------
// RMSNorm fp32 (+ optional residual)
// ---------------------------------------------------------------------------
__global__ __launch_bounds__(256) void rmsnorm_kernel(
    const float* __restrict__ in, const float* __restrict__ g,
    const float* __restrict__ res, float* __restrict__ out)
{
    int row = blockIdx.x;
    const float4* x4 = (const float4*)(in + (size_t)row * HH);
    const float4* g4 = (const float4*)g;
    const float4* r4 = res ? (const float4*)(res + (size_t)row * HH) : nullptr;
    float4* o4 = (float4*)(out + (size_t)row * HH);
    int t = threadIdx.x;

    float ss = 0.f;
    for (int i = t; i < HH / 4; i += 256) {
        float4 v = x4[i];
        ss += v.x * v.x + v.y * v.y + v.z * v.z + v.w * v.w;
    }
    #pragma unroll
    for (int off = 16; off > 0; off >>= 1)
        ss += __shfl_xor_sync(0xffffffffu, ss, off);
    __shared__ float red[8];
    __shared__ float s_inv;
    if ((t & 31) == 0) red[t >> 5] = ss;
    __syncthreads();
    if (t == 0) {
        float tot = 0.f;
        #pragma unroll
        for (int i = 0; i < 8; i++) tot += red[i];
        s_inv = rsqrtf(tot / (float)HH + RMS_EPS);
    }
    __syncthreads();
    float inv = s_inv;

    for (int i = t; i < HH / 4; i += 256) {
        float4 v = x4[i];
        float4 gv = g4[i];
        float4 o;
        o.x = v.x * inv * (1.f + gv.x);
        o.y = v.y * inv * (1.f + gv.y);
        o.z = v.z * inv * (1.f + gv.z);
        o.w = v.w * inv * (1.f + gv.w);
        if (r4) {
            float4 rv = r4[i];
            o.x += rv.x; o.y += rv.y; o.z += rv.z; o.w += rv.w;
        }
        o4[i] = o;
    }
}

// ---------------------------------------------------------------------------
// RMSNorm -> bf16 split output
// ---------------------------------------------------------------------------
__global__ __launch_bounds__(256) void rmsnorm_split_kernel(
    const float* __restrict__ in, const float* __restrict__ g,
    __nv_bfloat16* __restrict__ oh, __nv_bfloat16* __restrict__ ol)
{
    int row = blockIdx.x;
    const float4* x4 = (const float4*)(in + (size_t)row * HH);
    const float4* g4 = (const float4*)g;
    int t = threadIdx.x;

    float ss = 0.f;
    for (int i = t; i < HH / 4; i += 256) {
        float4 v = x4[i];
        ss += v.x * v.x + v.y * v.y + v.z * v.z + v.w * v.w;
    }
    #pragma unroll
    for (int off = 16; off > 0; off >>= 1)
        ss += __shfl_xor_sync(0xffffffffu, ss, off);
    __shared__ float red[8];
    __shared__ float s_inv;
    if ((t & 31) == 0) red[t >> 5] = ss;
    __syncthreads();
    if (t == 0) {
        float tot = 0.f;
        #pragma unroll
        for (int i = 0; i < 8; i++) tot += red[i];
        s_inv = rsqrtf(tot / (float)HH + RMS_EPS);
    }
    __syncthreads();
    float inv = s_inv;

    for (int i = t; i < HH / 4; i += 256) {
        float4 v = x4[i];
        float4 gv = g4[i];
        float y[4] = {v.x * inv * (1.f + gv.x), v.y * inv * (1.f + gv.y),
                      v.z * inv * (1.f + gv.z), v.w * inv * (1.f + gv.w)};
        BF4 hh, ll;
        #pragma unroll
        for (int j = 0; j < 4; j++) split_bf16(y[j], hh.b[j], ll.b[j]);
        *(uint2*)(oh + (size_t)row * HH + i * 4) = hh.u;
        *(uint2*)(ol + (size_t)row * HH + i * 4) = ll.u;
    }
}

// ---------------------------------------------------------------------------
// RoPE in place (fp32)
// ---------------------------------------------------------------------------
__global__ void rope_kernel(float* __restrict__ buf, int nh, int total)
{
    int idx = blockIdx.x * blockDim.x + threadIdx.x;
    if (idx >= total) return;
    int d = idx & 127;
    int rest = idx >> 7;
    int head = rest % nh;
    int tok = rest / nh;
    int pos = tok & (SS - 1);

    float inv = exp2f(-(float)(2 * d) * (13.287712379549449f / (float)HD));
    float ang = (float)pos * inv;
    float s, c;
    sincosf(ang, &s, &c);

    float* p = buf + (size_t)tok * (nh * HD) + head * HD + d;
    float lo = p[0];
    float hi = p[128];
    p[0]   = lo * c - hi * s;
    p[128] = hi * c + lo * s;
}

// ---------------------------------------------------------------------------
// Flash attention (fp32), epilogue emits bf16 split output for the O-proj GEMM
// ---------------------------------------------------------------------------
#define FA_BQ 64
#define FA_BK 32
__global__ __launch_bounds__(256) void flash_kernel(
    const float* __restrict__ Q, const float* __restrict__ K,
    const float* __restrict__ V,
    __nv_bfloat16* __restrict__ Oh, __nv_bfloat16* __restrict__ Ol)
{
    extern __shared__ float sm[];
    float* Ks = sm;
    float* Vs = sm + FA_BK * HD;
    float* Sp = sm + 2 * FA_BK * HD;

    int t = threadIdx.x;
    int r = t >> 2;
    int cp = t & 3;
    int q0 = blockIdx.x * FA_BQ;
    int h = blockIdx.y;
    int b = blockIdx.z;
    int kvh = h >> 1;
    int qg = q0 + r;

    float qr[64];
    {
        const float* qp = Q + ((size_t)(b * SS + qg) * QDIM) + h * HD + cp * 64;
        #pragma unroll
        for (int i = 0; i < 16; i++) {
            float4 v4 = *(const float4*)(qp + i * 4);
            qr[i * 4 + 0] = v4.x; qr[i * 4 + 1] = v4.y;
            qr[i * 4 + 2] = v4.z; qr[i * 4 + 3] = v4.w;
        }
    }

    float o[64];
    #pragma unroll
    for (int i = 0; i < 64; i++) o[i] = 0.f;
    float m = -INFINITY, l = 0.f;

    int ntiles = q0 / FA_BK + 2;

    for (int kt = 0; kt < ntiles; kt++) {
        int base = kt * FA_BK;
        #pragma unroll
        for (int i = 0; i < 8; i++) {
            int e = t + i * 256;
            int krow = e >> 6;
            int kcol = (e & 63) * 4;
            size_t goff = ((size_t)(b * SS + base + krow) * KVDIM) + kvh * HD + kcol;
            *(float4*)&Ks[krow * HD + kcol] = *(const float4*)(K + goff);
            *(float4*)&Vs[krow * HD + kcol] = *(const float4*)(V + goff);
        }
        __syncthreads();

        float tmax = -INFINITY;
        #pragma unroll 4
        for (int kk = 0; kk < FA_BK; kk++) {
            const float* kr = &Ks[kk * HD + cp * 64];
            float acc = 0.f;
            #pragma unroll
            for (int i = 0; i < 16; i++) {
                float4 k4 = *(const float4*)(kr + i * 4);
                acc = fmaf(qr[i * 4 + 0], k4.x, acc);
                acc = fmaf(qr[i * 4 + 1], k4.y, acc);
                acc = fmaf(qr[i * 4 + 2], k4.z, acc);
                acc = fmaf(qr[i * 4 + 3], k4.w, acc);
            }
            acc += __shfl_xor_sync(0xffffffffu, acc, 1);
            acc += __shfl_xor_sync(0xffffffffu, acc, 2);
            float sc = acc * ATT_SCALE;
            sc = SOFTCAP * tanhf(sc * (1.0f / SOFTCAP));
            int kg = base + kk;
            if (kg > qg) sc = -INFINITY;
            tmax = fmaxf(tmax, sc);
            if (cp == 0) Sp[r * FA_BK + kk] = sc;
        }
        __syncwarp();

        float mn = fmaxf(m, tmax);
        float alpha = __expf(m - mn);
        m = mn;
        l *= alpha;
        #pragma unroll
        for (int i = 0; i < 64; i++) o[i] *= alpha;

        #pragma unroll 2
        for (int kk = 0; kk < FA_BK; kk++) {
            float p = __expf(Sp[r * FA_BK + kk] - mn);
            l += p;
            const float* vr = &Vs[kk * HD + cp * 64];
            #pragma unroll
            for (int i = 0; i < 16; i++) {
                float4 v4 = *(const float4*)(vr + i * 4);
                o[i * 4 + 0] = fmaf(p, v4.x, o[i * 4 + 0]);
                o[i * 4 + 1] = fmaf(p, v4.y, o[i * 4 + 1]);
                o[i * 4 + 2] = fmaf(p, v4.z, o[i * 4 + 2]);
                o[i * 4 + 3] = fmaf(p, v4.w, o[i * 4 + 3]);
            }
        }
        __syncthreads();
    }

    float invl = 1.f / l;
    size_t obase = ((size_t)(b * SS + qg) * QDIM) + h * HD + cp * 64;
    #pragma unroll
    for (int i = 0; i < 16; i++) {
        BF4 hh, ll;
        #pragma unroll
        for (int j = 0; j < 4; j++) {
            float v = o[i * 4 + j] * invl;
            split_bf16(v, hh.b[j], ll.b[j]);
        }
        *(uint2*)(Oh + obase + i * 4) = hh.u;
        *(uint2*)(Ol + obase + i * 4) = ll.u;
    }
}

// ---------------------------------------------------------------------------
// GeGLU -> bf16 split output
// ---------------------------------------------------------------------------
__global__ void geglu_split_kernel(const float* __restrict__ gate,
                                   const float* __restrict__ up,
                                   __nv_bfloat16* __restrict__ gh,
                                   __nv_bfloat16* __restrict__ gl, int n4)
{
    int i = blockIdx.x * blockDim.x + threadIdx.x;
    if (i >= n4) return;
    float4 g4 = ((const float4*)gate)[i];
    float4 u4 = ((const float4*)up)[i];
    float gv[4] = {g4.x, g4.y, g4.z, g4.w};
    float uv[4] = {u4.x, u4.y, u4.z, u4.w};
    BF4 hh, ll;
    #pragma unroll
    for (int j = 0; j < 4; j++) {
        float x = gv[j];
        float x3 = x * x * x;
        float tg = tanhf(0.7978845608028654f * (x + 0.044715f * x3));
        float v = 0.5f * x * (1.f + tg) * uv[j];
        split_bf16(v, hh.b[j], ll.b[j]);
    }
    ((uint2*)gh)[i] = hh.u;
    ((uint2*)gl)[i] = ll.u;
}

// ---------------------------------------------------------------------------
// launch
// ---------------------------------------------------------------------------
static inline void launch_tc_gemm(const __nv_bfloat16* Ah, const __nv_bfloat16* Al,
                                  const __nv_bfloat16* Bh, const __nv_bfloat16* Bl,
                                  float* C, int M, int N, int K)
{
    dim3 grid(N / 128, M / 128);
    tc_gemm<<<grid, 256, GT_SMEM>>>(Ah, Al, Bh, Bl, C, M, N, K);
}

extern "C" void kernel_launch(void* const* d_in, const int* in_sizes, int n_in,
                              void* d_out, int out_size)
{
    const float* x      = (const float*)d_in[0];
    // d_in[1] = mask (causal, reconstructed in-kernel)
    const float* wq     = (const float*)d_in[2];
    const float* wk     = (const float*)d_in[3];
    const float* wv     = (const float*)d_in[4];
    const float* wo     = (const float*)d_in[5];
    const float* w_gate = (const float*)d_in[6];
    const float* w_up   = (const float*)d_in[7];
    const float* w_down = (const float*)d_in[8];
    const float* gin    = (const float*)d_in[9];
    const float* gpa    = (const float*)d_in[10];
    const float* gpf    = (const float*)d_in[11];
    const float* gpo    = (const float*)d_in[12];
    float* out = (float*)d_out;

    float *p_q, *p_k, *p_v, *p_att, *p_h2, *p_gate, *p_up, *p_mlp;
    cudaGetSymbolAddress((void**)&p_q,    g_q);
    cudaGetSymbolAddress((void**)&p_k,    g_k);
    cudaGetSymbolAddress((void**)&p_v,    g_v);
    cudaGetSymbolAddress((void**)&p_att,  g_att);
    cudaGetSymbolAddress((void**)&p_h2,   g_h2);
    cudaGetSymbolAddress((void**)&p_gate, g_gate);
    cudaGetSymbolAddress((void**)&p_up,   g_up);
    cudaGetSymbolAddress((void**)&p_mlp,  g_mlp);

    __nv_bfloat16 *hh, *hl, *oh, *ol, *fh, *fl, *gh, *gl;
    cudaGetSymbolAddress((void**)&hh, s_hh);  cudaGetSymbolAddress((void**)&hl, s_hl);
    cudaGetSymbolAddress((void**)&oh, s_oh);  cudaGetSymbolAddress((void**)&ol, s_ol);
    cudaGetSymbolAddress((void**)&fh, s_fh);  cudaGetSymbolAddress((void**)&fl, s_fl);
    cudaGetSymbolAddress((void**)&gh, s_gh);  cudaGetSymbolAddress((void**)&gl, s_gl);

    __nv_bfloat16 *qh, *ql, *kh, *kl, *vh, *vl, *ohw, *olw, *ghw, *glw, *uh, *ul, *dh, *dl;
    cudaGetSymbolAddress((void**)&qh, t_qh);  cudaGetSymbolAddress((void**)&ql, t_ql);
    cudaGetSymbolAddress((void**)&kh, t_kh);  cudaGetSymbolAddress((void**)&kl, t_kl);
    cudaGetSymbolAddress((void**)&vh, t_vh);  cudaGetSymbolAddress((void**)&vl, t_vl);
    cudaGetSymbolAddress((void**)&ohw, t_oh); cudaGetSymbolAddress((void**)&olw, t_ol);
    cudaGetSymbolAddress((void**)&ghw, t_gh); cudaGetSymbolAddress((void**)&glw, t_gl);
    cudaGetSymbolAddress((void**)&uh, t_uh);  cudaGetSymbolAddress((void**)&ul, t_ul);
    cudaGetSymbolAddress((void**)&dh, t_dh);  cudaGetSymbolAddress((void**)&dl, t_dl);

    cudaFuncSetAttribute(tc_gemm, cudaFuncAttributeMaxDynamicSharedMemorySize, GT_SMEM);
    static const int FLASH_SMEM = (2 * FA_BK * HD + FA_BQ * FA_BK) * 4; // 73728
    cudaFuncSetAttribute(flash_kernel,
                         cudaFuncAttributeMaxDynamicSharedMemorySize, FLASH_SMEM);

    // 0. weight prep: transpose + bf16 split (deterministic each call)
    dim3 wb(32, 8);
    wprep_kernel<<<dim3(QDIM / 32, HH / 32), wb>>>(wq,     qh,  ql,  HH,   QDIM);
    wprep_kernel<<<dim3(KVDIM / 32, HH / 32), wb>>>(wk,    kh,  kl,  HH,   KVDIM);
    wprep_kernel<<<dim3(KVDIM / 32, HH / 32), wb>>>(wv,    vh,  vl,  HH,   KVDIM);
    wprep_kernel<<<dim3(HH / 32, QDIM / 32), wb>>>(wo,     ohw, olw, QDIM, HH);
    wprep_kernel<<<dim3(FF / 32, HH / 32), wb>>>(w_gate,   ghw, glw, HH,   FF);
    wprep_kernel<<<dim3(FF / 32, HH / 32), wb>>>(w_up,     uh,  ul,  HH,   FF);
    wprep_kernel<<<dim3(HH / 32, FF / 32), wb>>>(w_down,   dh,  dl,  FF,   HH);

    // 1. h = rmsnorm(x, g_in) -> bf16 split
    rmsnorm_split_kernel<<<NTOK, 256>>>(x, gin, hh, hl);

    // 2. QKV projections (tensor cores)
    launch_tc_gemm(hh, hl, qh, ql, p_q, NTOK, QDIM, HH);
    launch_tc_gemm(hh, hl, kh, kl, p_k, NTOK, KVDIM, HH);
    launch_tc_gemm(hh, hl, vh, vl, p_v, NTOK, KVDIM, HH);

    // 3. RoPE in place
    {
        int tq = NTOK * NHEAD * 128;
        rope_kernel<<<(tq + 255) / 256, 256>>>(p_q, NHEAD, tq);
        int tk = NTOK * NKV * 128;
        rope_kernel<<<(tk + 255) / 256, 256>>>(p_k, NKV, tk);
    }

    // 4. attention -> bf16 split output
    {
        dim3 grid(SS / FA_BQ, NHEAD, BB);
        flash_kernel<<<grid, 256, FLASH_SMEM>>>(p_q, p_k, p_v, oh, ol);
    }

    // 5. output projection
    launch_tc_gemm(oh, ol, ohw, olw, p_att, NTOK, HH, QDIM);

    // 6. h2 = x + rmsnorm(att, g_post_attn)
    rmsnorm_kernel<<<NTOK, 256>>>(p_att, gpa, x, p_h2);

    // 7. f = rmsnorm(h2, g_pre_ff) -> bf16 split
    rmsnorm_split_kernel<<<NTOK, 256>>>(p_h2, gpf, fh, fl);

    // 8. MLP
    launch_tc_gemm(fh, fl, ghw, glw, p_gate, NTOK, FF, HH);
    launch_tc_gemm(fh, fl, uh,  ul,  p_up,   NTOK, FF, HH);
    {
        int n4 = NTOK * FF / 4;
        geglu_split_kernel<<<(n4 + 255) / 256, 256>>>(p_gate, p_up, gh, gl, n4);
    }
    launch_tc_gemm(gh, gl, dh, dl, p_mlp, NTOK, HH, FF);

    // 9. out = h2 + rmsnorm(mlp, g_post_ff)
    rmsnorm_kernel<<<NTOK, 256>>>(p_mlp, gpo, p_h2, out);
}